// round 10
// baseline (speedup 1.0000x reference)
#include <cuda_runtime.h>
#include <cuda_fp16.h>
#include <cstdint>
#include <math.h>

#define BB 4
#define LL 2048
#define DD 1024
#define HH 16
#define KK 256
#define DH 64
#define MROWS (BB*LL)   // 8192

// ---- scratch (device globals; no runtime allocation allowed) ----
__device__ float g_q[BB*LL*DD];        // x @ Wq^T            [B,L,D]
__device__ float g_xkt[BB*DD*LL];      // (x @ Wk^T)^T        [B,D,L]
__device__ float g_xvt[BB*DD*LL];      // (x @ Wv^T)^T        [B,D,L]
__device__ float g_projkt[KK*LL];      // proj_k^T            [K,L]
__device__ float g_projvt[KK*LL];      // proj_v^T            [K,L]
__device__ float g_keys2[2*BB*KK*DD];  // split-K partials (summed in attn)
__device__ float g_vals2[2*BB*KK*DD];
__device__ float g_ctx[BB*LL*DD];      // attention out       [B,L,D]

// ============================================================
// helpers
// ============================================================
__device__ __forceinline__ uint32_t smem_u32(const void* p) {
    uint32_t a;
    asm("{ .reg .u64 t; cvta.to.shared.u64 t, %1; cvt.u32.u64 %0, t; }"
        : "=r"(a) : "l"(p));
    return a;
}
__device__ __forceinline__ void ldsm4(uint32_t* r, uint32_t addr) {
    asm volatile("ldmatrix.sync.aligned.m8n8.x4.shared.b16 {%0,%1,%2,%3}, [%4];"
        : "=r"(r[0]), "=r"(r[1]), "=r"(r[2]), "=r"(r[3]) : "r"(addr));
}
__device__ __forceinline__ void ldsm2(uint32_t* r, uint32_t addr) {
    asm volatile("ldmatrix.sync.aligned.m8n8.x2.shared.b16 {%0,%1}, [%2];"
        : "=r"(r[0]), "=r"(r[1]) : "r"(addr));
}
__device__ __forceinline__ void ldsm2t(uint32_t* r, uint32_t addr) {
    asm volatile("ldmatrix.sync.aligned.m8n8.x2.trans.shared.b16 {%0,%1}, [%2];"
        : "=r"(r[0]), "=r"(r[1]) : "r"(addr));
}
__device__ __forceinline__ void mma16816(float* c, const uint32_t* a, const uint32_t* b) {
    asm volatile(
        "mma.sync.aligned.m16n8k16.row.col.f32.f16.f16.f32 "
        "{%0,%1,%2,%3}, {%4,%5,%6,%7}, {%8,%9}, {%0,%1,%2,%3};"
        : "+f"(c[0]), "+f"(c[1]), "+f"(c[2]), "+f"(c[3])
        : "r"(a[0]), "r"(a[1]), "r"(a[2]), "r"(a[3]), "r"(b[0]), "r"(b[1]));
}
#define BAR_SYNC(id)    asm volatile("bar.sync %0, 384;"   :: "r"(id) : "memory")
#define BAR_ARRIVE(id)  asm volatile("bar.arrive %0, 384;" :: "r"(id) : "memory")
#define BAR_SYNC2(id)   asm volatile("bar.sync %0, 320;"   :: "r"(id) : "memory")
#define BAR_ARRIVE2(id) asm volatile("bar.arrive %0, 320;" :: "r"(id) : "memory")

// split 8 f32 -> 16B hi chunk + 16B lo chunk
__device__ __forceinline__ void cvt_split16(float4 a, float4 b, uint4& hi, uint4& lo) {
    __half2 h0 = __floats2half2_rn(a.x, a.y);
    __half2 h1 = __floats2half2_rn(a.z, a.w);
    __half2 h2 = __floats2half2_rn(b.x, b.y);
    __half2 h3 = __floats2half2_rn(b.z, b.w);
    float2 f0 = __half22float2(h0);
    float2 f1 = __half22float2(h1);
    float2 f2 = __half22float2(h2);
    float2 f3 = __half22float2(h3);
    __half2 l0 = __floats2half2_rn(a.x - f0.x, a.y - f0.y);
    __half2 l1 = __floats2half2_rn(a.z - f1.x, a.w - f1.y);
    __half2 l2 = __floats2half2_rn(b.x - f2.x, b.y - f2.y);
    __half2 l3 = __floats2half2_rn(b.z - f3.x, b.w - f3.y);
    hi.x = *(uint32_t*)&h0; hi.y = *(uint32_t*)&h1;
    hi.z = *(uint32_t*)&h2; hi.w = *(uint32_t*)&h3;
    lo.x = *(uint32_t*)&l0; lo.y = *(uint32_t*)&l1;
    lo.z = *(uint32_t*)&l2; lo.w = *(uint32_t*)&l3;
}
// round 8 f32 -> 16B fp16 chunk (hi only)
__device__ __forceinline__ void cvt_hi16(float4 a, float4 b, uint4& hi) {
    __half2 h0 = __floats2half2_rn(a.x, a.y);
    __half2 h1 = __floats2half2_rn(a.z, a.w);
    __half2 h2 = __floats2half2_rn(b.x, b.y);
    __half2 h3 = __floats2half2_rn(b.z, b.w);
    hi.x = *(uint32_t*)&h0; hi.y = *(uint32_t*)&h1;
    hi.z = *(uint32_t*)&h2; hi.w = *(uint32_t*)&h3;
}

// ============================================================
// WIDE warp-specialized 2-MMA split GEMM (big GEMMs):
// C = Ah*Bh + Ah*Bl. CTA tile 128(M) x 256(N), BK=32.
// 320 threads: warps 0-7 consumers (warp tile 64x64), warps 8-9 producers.
// XOR-swizzled 64B rows; 3-stage ring.
// ============================================================
#define T2B   8192                    // A tile: 128 rows x 64B
#define BT2B  16384                   // B tile per plane: 256 rows x 64B
#define STG2B (T2B + 2*BT2B)          // 40960
#define NSTG2 3
#define GEMM2_SMEM (NSTG2*STG2B)      // 122880

template<bool BIAS>
__global__ __launch_bounds__(320, 1)
void gemm_ws256(const float* __restrict__ A, long Ab, int lda,
                const float* __restrict__ B, long Bb, int ldb,
                float* __restrict__ C, long Cb, int ldc,
                const float* __restrict__ bias, int Kd)
{
    extern __shared__ __align__(16) char smc[];

    const int tid  = threadIdx.x;
    const int lane = tid & 31;
    const int wid  = tid >> 5;

    A += (size_t)blockIdx.z * Ab;
    B += (size_t)blockIdx.z * Bb;
    C += (size_t)blockIdx.z * Cb;
    const int m0 = blockIdx.y * 128;
    const int n0 = blockIdx.x * 256;
    const int iters = Kd / 32;

    if (wid >= 8) {
        // ================= producers (2 warps, 64 threads) =================
        const int ptid = tid - 256;                   // 0..63
        const float* Aip = A + (size_t)m0 * lda;
        const float* Bip = B + (size_t)n0 * ldb;

        for (int it = 0; it < iters; it++) {
            const int s = it % NSTG2;
            if (it >= NSTG2) BAR_SYNC2(4 + s);        // EMPTY(s)
            const int k0 = it * 32;
            char* stg = smc + s * STG2B;
            // A: 512 hi chunks, 8 per thread
            #pragma unroll
            for (int p = 0; p < 8; p++) {
                int idx = ptid + p * 64;              // 0..511
                int r = idx >> 2, c = idx & 3;
                int sw = (c ^ ((r >> 1) & 3)) * 16;
                const float* src = Aip + (size_t)r * lda + k0 + c * 8;
                float4 v0 = *(const float4*)src;
                float4 v1 = *(const float4*)(src + 4);
                uint4 hi;
                cvt_hi16(v0, v1, hi);
                *(uint4*)(stg + r * 64 + sw) = hi;
            }
            // B: 1024 chunk positions, hi+lo, 16 per thread
            #pragma unroll
            for (int p = 0; p < 16; p++) {
                int idx = ptid + p * 64;              // 0..1023
                int r = idx >> 2, c = idx & 3;
                int sw = (c ^ ((r >> 1) & 3)) * 16;
                const float* src = Bip + (size_t)r * ldb + k0 + c * 8;
                float4 v0 = *(const float4*)src;
                float4 v1 = *(const float4*)(src + 4);
                uint4 hi, lo;
                cvt_split16(v0, v1, hi, lo);
                *(uint4*)(stg + T2B + r * 64 + sw) = hi;
                *(uint4*)(stg + T2B + BT2B + r * 64 + sw) = lo;
            }
            BAR_ARRIVE2(1 + s);                       // FULL(s)
        }
    } else {
        // ================= consumers (8 warps, warp tile 64x64) ============
        const int wm = wid >> 2;                      // 0..1
        const int wn = wid & 3;                       // 0..3
        const int g  = lane >> 2;
        const int tig = lane & 3;
        const uint32_t sbase = smem_u32(smc);

        float acc[4][8][4];
        #pragma unroll
        for (int i = 0; i < 4; i++)
            #pragma unroll
            for (int j = 0; j < 8; j++)
                #pragma unroll
                for (int v = 0; v < 4; v++) acc[i][j][v] = 0.f;

        for (int it = 0; it < iters; it++) {
            const int s = it % NSTG2;
            BAR_SYNC2(1 + s);                         // FULL(s)
            const uint32_t stg = sbase + s * STG2B;

            #pragma unroll
            for (int ks = 0; ks < 2; ks++) {
                uint32_t ah[4][4], bh[8][2], bl[8][2];
                const int cA = ks * 2 + (lane >> 4);
                #pragma unroll
                for (int mi = 0; mi < 4; mi++) {
                    int r = wm * 64 + mi * 16 + (lane & 15);
                    uint32_t off = (uint32_t)(r * 64 + ((cA ^ ((r >> 1) & 3)) << 4));
                    ldsm4(ah[mi], stg + off);
                }
                const int cB = ks * 2 + ((lane >> 3) & 1);
                #pragma unroll
                for (int ni = 0; ni < 8; ni++) {
                    int r = wn * 64 + ni * 8 + (lane & 7);
                    uint32_t off = (uint32_t)(r * 64 + ((cB ^ ((r >> 1) & 3)) << 4));
                    ldsm2(bh[ni], stg + T2B + off);
                    ldsm2(bl[ni], stg + T2B + BT2B + off);
                }
                #pragma unroll
                for (int mi = 0; mi < 4; mi++)
                    #pragma unroll
                    for (int ni = 0; ni < 8; ni++) {
                        mma16816(acc[mi][ni], ah[mi], bh[ni]);
                        mma16816(acc[mi][ni], ah[mi], bl[ni]);
                    }
            }
            BAR_ARRIVE2(4 + s);                       // EMPTY(s)
        }

        // ---- epilogue ----
        #pragma unroll
        for (int mi = 0; mi < 4; mi++) {
            const int r0 = m0 + wm * 64 + mi * 16 + g;
            #pragma unroll
            for (int ni = 0; ni < 8; ni++) {
                const int col = n0 + wn * 64 + ni * 8 + tig * 2;
                float2 v0, v1;
                v0.x = acc[mi][ni][0]; v0.y = acc[mi][ni][1];
                v1.x = acc[mi][ni][2]; v1.y = acc[mi][ni][3];
                if (BIAS) {
                    float2 bv = *(const float2*)(bias + col);
                    v0.x += bv.x; v0.y += bv.y;
                    v1.x += bv.x; v1.y += bv.y;
                }
                *(float2*)(C + (size_t)r0 * ldc + col) = v0;
                *(float2*)(C + (size_t)(r0 + 8) * ldc + col) = v1;
            }
        }
    }
}

// ============================================================
// 128x128 warp-specialized 2-MMA split GEMM (proj GEMMs, R9-proven)
// ============================================================
#define TILEB 8192
#define STGB  (3*TILEB)
#define NSTG  3
#define GEMM_SMEM (NSTG*STGB)        // 73728

__global__ __launch_bounds__(384, 1)
void gemm_ws(const float* __restrict__ A, long Ab, int lda,
             const float* __restrict__ B, long Bb, int ldb,
             float* __restrict__ C, long Cb, long Cs, int ldc,
             int Kd, int ksp)
{
    extern __shared__ __align__(16) char smc[];

    const int tid  = threadIdx.x;
    const int lane = tid & 31;
    const int wid  = tid >> 5;

    const int zb = blockIdx.z / ksp;
    const int zs = blockIdx.z % ksp;
    A += (size_t)zb * Ab + (size_t)zs * Kd;
    B += (size_t)zb * Bb + (size_t)zs * Kd;
    C += (size_t)zb * Cb + (size_t)zs * Cs;
    const int m0 = blockIdx.y * 128;
    const int n0 = blockIdx.x * 128;
    const int iters = Kd / 32;

    if (wid >= 8) {
        const int ptid = tid - 256;
        const float* Aip = A + (size_t)m0 * lda;
        const float* Bip = B + (size_t)n0 * ldb;

        for (int it = 0; it < iters; it++) {
            const int s = it % NSTG;
            if (it >= NSTG) BAR_SYNC(4 + s);
            const int k0 = it * 32;
            char* stg = smc + s * STGB;
            #pragma unroll
            for (int p = 0; p < 4; p++) {
                int idx = ptid + p * 128;
                int r = idx >> 2, c = idx & 3;
                int sw = (c ^ ((r >> 1) & 3)) * 16;
                {
                    const float* src = Aip + (size_t)r * lda + k0 + c * 8;
                    float4 v0 = *(const float4*)src;
                    float4 v1 = *(const float4*)(src + 4);
                    uint4 hi;
                    cvt_hi16(v0, v1, hi);
                    *(uint4*)(stg + r * 64 + sw) = hi;
                }
                {
                    const float* src = Bip + (size_t)r * ldb + k0 + c * 8;
                    float4 v0 = *(const float4*)src;
                    float4 v1 = *(const float4*)(src + 4);
                    uint4 hi, lo;
                    cvt_split16(v0, v1, hi, lo);
                    *(uint4*)(stg + TILEB + r * 64 + sw) = hi;
                    *(uint4*)(stg + 2*TILEB + r * 64 + sw) = lo;
                }
            }
            BAR_ARRIVE(1 + s);
        }
    } else {
        const int wm = wid >> 2;
        const int wn = wid & 3;
        const int g  = lane >> 2;
        const int tig = lane & 3;
        const uint32_t sbase = smem_u32(smc);

        float acc[4][4][4];
        #pragma unroll
        for (int i = 0; i < 4; i++)
            #pragma unroll
            for (int j = 0; j < 4; j++)
                #pragma unroll
                for (int v = 0; v < 4; v++) acc[i][j][v] = 0.f;

        for (int it = 0; it < iters; it++) {
            const int s = it % NSTG;
            BAR_SYNC(1 + s);
            const uint32_t stg = sbase + s * STGB;

            uint32_t ah[2][4][4], bh[2][4][2], bl[2][4][2];
            #pragma unroll
            for (int ks = 0; ks < 2; ks++) {
                const int cA = ks * 2 + (lane >> 4);
                #pragma unroll
                for (int mi = 0; mi < 4; mi++) {
                    int r = wm * 64 + mi * 16 + (lane & 15);
                    uint32_t off = (uint32_t)(r * 64 + ((cA ^ ((r >> 1) & 3)) << 4));
                    ldsm4(ah[ks][mi], stg + off);
                }
                const int cB = ks * 2 + ((lane >> 3) & 1);
                #pragma unroll
                for (int ni = 0; ni < 4; ni++) {
                    int r = wn * 32 + ni * 8 + (lane & 7);
                    uint32_t off = (uint32_t)(r * 64 + ((cB ^ ((r >> 1) & 3)) << 4));
                    ldsm2(bh[ks][ni], stg + TILEB + off);
                    ldsm2(bl[ks][ni], stg + 2*TILEB + off);
                }
            }
            #pragma unroll
            for (int ks = 0; ks < 2; ks++)
                #pragma unroll
                for (int mi = 0; mi < 4; mi++)
                    #pragma unroll
                    for (int ni = 0; ni < 4; ni++) {
                        mma16816(acc[mi][ni], ah[ks][mi], bh[ks][ni]);
                        mma16816(acc[mi][ni], ah[ks][mi], bl[ks][ni]);
                    }
            BAR_ARRIVE(4 + s);
        }

        #pragma unroll
        for (int mi = 0; mi < 4; mi++) {
            const int r0 = m0 + wm * 64 + mi * 16 + g;
            #pragma unroll
            for (int ni = 0; ni < 4; ni++) {
                const int col = n0 + wn * 32 + ni * 8 + tig * 2;
                float2 v0, v1;
                v0.x = acc[mi][ni][0]; v0.y = acc[mi][ni][1];
                v1.x = acc[mi][ni][2]; v1.y = acc[mi][ni][3];
                *(float2*)(C + (size_t)r0 * ldc + col) = v0;
                *(float2*)(C + (size_t)(r0 + 8) * ldc + col) = v1;
            }
        }
    }
}

// ============================================================
// proj transpose: [L,K] -> [K,L]
// ============================================================
__global__ __launch_bounds__(256)
void transpose_proj(const float* __restrict__ pk, const float* __restrict__ pv,
                    float* __restrict__ okt, float* __restrict__ ovt)
{
    __shared__ float t[32][33];
    const float* src = blockIdx.z ? pv : pk;
    float* dst       = blockIdx.z ? ovt : okt;
    int k0 = blockIdx.x * 32, l0 = blockIdx.y * 32;
    int tx = threadIdx.x, ty = threadIdx.y;
    #pragma unroll
    for (int i = 0; i < 32; i += 8)
        t[ty + i][tx] = src[(size_t)(l0 + ty + i) * KK + k0 + tx];
    __syncthreads();
    #pragma unroll
    for (int i = 0; i < 32; i += 8)
        dst[(size_t)(k0 + ty + i) * LL + l0 + tx] = t[tx][ty + i];
}

// ============================================================
// MMA attention (XOR-swizzled smem); split-K reduction FUSED into the
// K/V smem fill (reads both keys2/vals2 partials, adds, splits).
// ============================================================
#define AQH 0
#define AQL 16384
#define AKH 32768
#define AKL 65536
#define AVH 98304
#define AVL 131072
#define ATTN_SMEM 163840

__global__ __launch_bounds__(256, 1)
void attn_mma()
{
    extern __shared__ __align__(16) char smc[];
    const uint32_t base = smem_u32(smc);

    const int b  = blockIdx.z;
    const int h  = blockIdx.y;
    const int l0 = blockIdx.x * 128;
    const int tid  = threadIdx.x;
    const int lane = tid & 31;
    const int wy   = tid >> 5;
    const int g    = lane >> 2;
    const int tig  = lane & 3;

    #pragma unroll
    for (int it = 0; it < 4; it++) {
        int idx = tid + it * 256;
        int r = idx >> 3, c = idx & 7;
        int l = l0 + r;
        const float* src = g_q + ((size_t)(b * LL) + h * 128 + (l >> 4)) * DD
                               + (l & 15) * DH + c * 8;
        float4 v0 = *(const float4*)src;
        float4 v1 = *(const float4*)(src + 4);
        uint4 hi, lo;
        cvt_split16(v0, v1, hi, lo);
        int sw = r * 128 + ((c ^ (r & 7)) << 4);
        *(uint4*)(smc + AQH + sw) = hi;
        *(uint4*)(smc + AQL + sw) = lo;
    }
    const size_t PART = (size_t)BB * KK * DD;
    #pragma unroll
    for (int it = 0; it < 8; it++) {
        int idx = tid + it * 256;
        int r = idx >> 3, c = idx & 7;
        size_t o = ((size_t)b * KK + r) * DD + h * DH + c * 8;
        float4 a0 = *(const float4*)&g_keys2[o];
        float4 a1 = *(const float4*)&g_keys2[o + 4];
        float4 b0 = *(const float4*)&g_keys2[PART + o];
        float4 b1 = *(const float4*)&g_keys2[PART + o + 4];
        a0.x += b0.x; a0.y += b0.y; a0.z += b0.z; a0.w += b0.w;
        a1.x += b1.x; a1.y += b1.y; a1.z += b1.z; a1.w += b1.w;
        uint4 hi, lo;
        cvt_split16(a0, a1, hi, lo);
        int sw = r * 128 + ((c ^ (r & 7)) << 4);
        *(uint4*)(smc + AKH + sw) = hi;
        *(uint4*)(smc + AKL + sw) = lo;
    }
    #pragma unroll
    for (int it = 0; it < 8; it++) {
        int idx = tid + it * 256;
        int r = idx >> 3, c = idx & 7;
        size_t o = ((size_t)b * KK + r) * DD + h * DH + c * 8;
        float4 a0 = *(const float4*)&g_vals2[o];
        float4 a1 = *(const float4*)&g_vals2[o + 4];
        float4 b0 = *(const float4*)&g_vals2[PART + o];
        float4 b1 = *(const float4*)&g_vals2[PART + o + 4];
        a0.x += b0.x; a0.y += b0.y; a0.z += b0.z; a0.w += b0.w;
        a1.x += b1.x; a1.y += b1.y; a1.z += b1.z; a1.w += b1.w;
        uint4 hi, lo;
        cvt_split16(a0, a1, hi, lo);
        int sw = r * 128 + ((c ^ (r & 7)) << 4);
        *(uint4*)(smc + AVH + sw) = hi;
        *(uint4*)(smc + AVL + sw) = lo;
    }
    __syncthreads();

    const int m0w = wy * 16;

    uint32_t qa_h[4][4], qa_l[4][4];
    {
        int r = m0w + (lane & 15);
        #pragma unroll
        for (int kt = 0; kt < 4; kt++) {
            int c = kt * 2 + (lane >> 4);
            uint32_t off = (uint32_t)(r * 128 + ((c ^ (r & 7)) << 4));
            ldsm4(qa_h[kt], base + AQH + off);
            ldsm4(qa_l[kt], base + AQL + off);
        }
    }

    float acc[32][4];
    #pragma unroll
    for (int nt = 0; nt < 32; nt++)
        #pragma unroll
        for (int v = 0; v < 4; v++) acc[nt][v] = 0.f;

    #pragma unroll
    for (int nt = 0; nt < 32; nt++) {
        int r = nt * 8 + (lane & 7);
        int c0 = (lane >> 3);
        uint32_t off1 = (uint32_t)(r * 128 + ((c0 ^ (r & 7)) << 4));
        uint32_t off2 = (uint32_t)(r * 128 + (((c0 + 4) ^ (r & 7)) << 4));
        uint32_t kh[8], kl[8];
        ldsm4(kh,     base + AKH + off1);
        ldsm4(kh + 4, base + AKH + off2);
        ldsm4(kl,     base + AKL + off1);
        ldsm4(kl + 4, base + AKL + off2);
        #pragma unroll
        for (int kt = 0; kt < 4; kt++) {
            mma16816(acc[nt], qa_h[kt], kh + kt * 2);
            mma16816(acc[nt], qa_h[kt], kl + kt * 2);
            mma16816(acc[nt], qa_l[kt], kh + kt * 2);
        }
    }

    const float SC = 0.125f;
    float mx0 = -1e30f, mx1 = -1e30f;
    #pragma unroll
    for (int nt = 0; nt < 32; nt++) {
        mx0 = fmaxf(mx0, fmaxf(acc[nt][0], acc[nt][1]));
        mx1 = fmaxf(mx1, fmaxf(acc[nt][2], acc[nt][3]));
    }
    #pragma unroll
    for (int o = 1; o <= 2; o <<= 1) {
        mx0 = fmaxf(mx0, __shfl_xor_sync(0xffffffffu, mx0, o));
        mx1 = fmaxf(mx1, __shfl_xor_sync(0xffffffffu, mx1, o));
    }
    const float b0s = mx0 * SC, b1s = mx1 * SC;
    float s0 = 0.f, s1 = 0.f;
    #pragma unroll
    for (int nt = 0; nt < 32; nt++) {
        acc[nt][0] = __expf(acc[nt][0] * SC - b0s);
        acc[nt][1] = __expf(acc[nt][1] * SC - b0s);
        acc[nt][2] = __expf(acc[nt][2] * SC - b1s);
        acc[nt][3] = __expf(acc[nt][3] * SC - b1s);
        s0 += acc[nt][0] + acc[nt][1];
        s1 += acc[nt][2] + acc[nt][3];
    }
    #pragma unroll
    for (int o = 1; o <= 2; o <<= 1) {
        s0 += __shfl_xor_sync(0xffffffffu, s0, o);
        s1 += __shfl_xor_sync(0xffffffffu, s1, o);
    }
    const float inv0 = 1.f / s0, inv1 = 1.f / s1;

    float oac[8][4];
    #pragma unroll
    for (int nj = 0; nj < 8; nj++)
        #pragma unroll
        for (int v = 0; v < 4; v++) oac[nj][v] = 0.f;

    #pragma unroll
    for (int kt = 0; kt < 16; kt++) {
        uint32_t ph[4], pl[4];
        #pragma unroll
        for (int half_ = 0; half_ < 2; half_++) {
            const float* c = acc[2 * kt + half_];
            __half2 h0 = __floats2half2_rn(c[0], c[1]);
            __half2 h1 = __floats2half2_rn(c[2], c[3]);
            float2 f0 = __half22float2(h0);
            float2 f1 = __half22float2(h1);
            __half2 e0 = __floats2half2_rn(c[0] - f0.x, c[1] - f0.y);
            __half2 e1 = __floats2half2_rn(c[2] - f1.x, c[3] - f1.y);
            ph[half_ * 2 + 0] = *(uint32_t*)&h0;
            ph[half_ * 2 + 1] = *(uint32_t*)&h1;
            pl[half_ * 2 + 0] = *(uint32_t*)&e0;
            pl[half_ * 2 + 1] = *(uint32_t*)&e1;
        }
        int rv = kt * 16 + (lane & 15);
        #pragma unroll
        for (int nj = 0; nj < 8; nj++) {
            uint32_t off = (uint32_t)(rv * 128 + ((nj ^ (rv & 7)) << 4));
            uint32_t vh[2], vl[2];
            ldsm2t(vh, base + AVH + off);
            ldsm2t(vl, base + AVL + off);
            mma16816(oac[nj], ph, vh);
            mma16816(oac[nj], ph, vl);
            mma16816(oac[nj], pl, vh);
        }
    }

    {
        const int r0 = l0 + m0w + g;
        const size_t orow = ((size_t)(b * LL) + r0) * DD + h * DH;
        #pragma unroll
        for (int nj = 0; nj < 8; nj++) {
            float2 v0, v1;
            v0.x = oac[nj][0] * inv0; v0.y = oac[nj][1] * inv0;
            v1.x = oac[nj][2] * inv1; v1.y = oac[nj][3] * inv1;
            *(float2*)&g_ctx[orow + nj * 8 + tig * 2] = v0;
            *(float2*)&g_ctx[orow + (size_t)8 * DD + nj * 8 + tig * 2] = v1;
        }
    }
}

// ============================================================
extern "C" void kernel_launch(void* const* d_in, const int* in_sizes, int n_in,
                              void* d_out, int out_size)
{
    const float* x      = (const float*)d_in[0];
    const float* Wq     = (const float*)d_in[1];
    const float* Wk     = (const float*)d_in[2];
    const float* Wv     = (const float*)d_in[3];
    const float* proj_k = (const float*)d_in[4];
    const float* proj_v = (const float*)d_in[5];
    const float* Wo     = (const float*)d_in[6];
    const float* bo     = (const float*)d_in[7];
    float* out = (float*)d_out;

    float *q, *xkt, *xvt, *projkt, *projvt, *keys2, *vals2, *ctx;
    cudaGetSymbolAddress((void**)&q,      g_q);
    cudaGetSymbolAddress((void**)&xkt,    g_xkt);
    cudaGetSymbolAddress((void**)&xvt,    g_xvt);
    cudaGetSymbolAddress((void**)&projkt, g_projkt);
    cudaGetSymbolAddress((void**)&projvt, g_projvt);
    cudaGetSymbolAddress((void**)&keys2,  g_keys2);
    cudaGetSymbolAddress((void**)&vals2,  g_vals2);
    cudaGetSymbolAddress((void**)&ctx,    g_ctx);

    cudaFuncSetAttribute(gemm_ws256<false>, cudaFuncAttributeMaxDynamicSharedMemorySize, GEMM2_SMEM);
    cudaFuncSetAttribute(gemm_ws256<true>,  cudaFuncAttributeMaxDynamicSharedMemorySize, GEMM2_SMEM);
    cudaFuncSetAttribute(gemm_ws,  cudaFuncAttributeMaxDynamicSharedMemorySize, GEMM_SMEM);
    cudaFuncSetAttribute(attn_mma, cudaFuncAttributeMaxDynamicSharedMemorySize, ATTN_SMEM);

    // proj_k / proj_v -> transposed [K,L]
    transpose_proj<<<dim3(KK/32, LL/32, 2), dim3(32, 8)>>>(proj_k, proj_v, projkt, projvt);

    // q = x @ Wq^T   [8192,1024]
    gemm_ws256<false><<<dim3(DD/256, MROWS/128, 1), 320, GEMM2_SMEM>>>(
        x, 0, DD, Wq, 0, DD, q, 0, DD, nullptr, DD);

    // xkt[b] = Wk x_b^T : [D, L]
    gemm_ws256<false><<<dim3(LL/256, DD/128, BB), 320, GEMM2_SMEM>>>(
        Wk, 0, DD, x, (long)LL*DD, DD, xkt, (long)DD*LL, LL, nullptr, DD);

    // xvt[b]
    gemm_ws256<false><<<dim3(LL/256, DD/128, BB), 320, GEMM2_SMEM>>>(
        Wv, 0, DD, x, (long)LL*DD, DD, xvt, (long)DD*LL, LL, nullptr, DD);

    // keys partials [zs][b][K,D] = projkt x xkt^T  (split-K over L)
    gemm_ws<<<dim3(DD/128, KK/128, BB*2), 384, GEMM_SMEM>>>(
        projkt, 0, LL, xkt, (long)DD*LL, LL,
        keys2, (long)KK*DD, (long)BB*KK*DD, DD, LL/2, 2);

    // vals partials [zs][b][K,D]
    gemm_ws<<<dim3(DD/128, KK/128, BB*2), 384, GEMM_SMEM>>>(
        projvt, 0, LL, xvt, (long)DD*LL, LL,
        vals2, (long)KK*DD, (long)BB*KK*DD, DD, LL/2, 2);

    // MMA attention (fuses the split-K adds)
    attn_mma<<<dim3(LL/128, HH, BB), 256, ATTN_SMEM>>>();

    // out = ctx @ Wo^T + bo
    gemm_ws256<true><<<dim3(DD/256, MROWS/128, 1), 320, GEMM2_SMEM>>>(
        ctx, 0, DD, Wo, 0, DD, out, 0, DD, bo, DD);
}

// round 11
// speedup vs baseline: 1.3967x; 1.3967x over previous
#include <cuda_runtime.h>
#include <cuda_fp16.h>
#include <cstdint>
#include <math.h>

#define BB 4
#define LL 2048
#define DD 1024
#define HH 16
#define KK 256
#define DH 64
#define MROWS (BB*LL)   // 8192

// ---- scratch (device globals; no runtime allocation allowed) ----
__device__ float g_q[BB*LL*DD];        // x @ Wq^T            [B,L,D]
__device__ float g_xkt[BB*DD*LL];      // (x @ Wk^T)^T        [B,D,L]
__device__ float g_xvt[BB*DD*LL];      // (x @ Wv^T)^T        [B,D,L]
__device__ float g_projkt[KK*LL];      // proj_k^T            [K,L]
__device__ float g_projvt[KK*LL];      // proj_v^T            [K,L]
__device__ float g_keys2[2*BB*KK*DD];  // split-K partials (summed in attn)
__device__ float g_vals2[2*BB*KK*DD];
__device__ float g_ctx[BB*LL*DD];      // attention out       [B,L,D]

// ============================================================
// helpers
// ============================================================
__device__ __forceinline__ uint32_t smem_u32(const void* p) {
    uint32_t a;
    asm("{ .reg .u64 t; cvta.to.shared.u64 t, %1; cvt.u32.u64 %0, t; }"
        : "=r"(a) : "l"(p));
    return a;
}
__device__ __forceinline__ void ldsm4(uint32_t* r, uint32_t addr) {
    asm volatile("ldmatrix.sync.aligned.m8n8.x4.shared.b16 {%0,%1,%2,%3}, [%4];"
        : "=r"(r[0]), "=r"(r[1]), "=r"(r[2]), "=r"(r[3]) : "r"(addr));
}
__device__ __forceinline__ void ldsm2(uint32_t* r, uint32_t addr) {
    asm volatile("ldmatrix.sync.aligned.m8n8.x2.shared.b16 {%0,%1}, [%2];"
        : "=r"(r[0]), "=r"(r[1]) : "r"(addr));
}
__device__ __forceinline__ void ldsm2t(uint32_t* r, uint32_t addr) {
    asm volatile("ldmatrix.sync.aligned.m8n8.x2.trans.shared.b16 {%0,%1}, [%2];"
        : "=r"(r[0]), "=r"(r[1]) : "r"(addr));
}
__device__ __forceinline__ void mma16816(float* c, const uint32_t* a, const uint32_t* b) {
    asm volatile(
        "mma.sync.aligned.m16n8k16.row.col.f32.f16.f16.f32 "
        "{%0,%1,%2,%3}, {%4,%5,%6,%7}, {%8,%9}, {%0,%1,%2,%3};"
        : "+f"(c[0]), "+f"(c[1]), "+f"(c[2]), "+f"(c[3])
        : "r"(a[0]), "r"(a[1]), "r"(a[2]), "r"(a[3]), "r"(b[0]), "r"(b[1]));
}
#define BAR_SYNC(id)   asm volatile("bar.sync %0, 384;"   :: "r"(id) : "memory")
#define BAR_ARRIVE(id) asm volatile("bar.arrive %0, 384;" :: "r"(id) : "memory")

// split 8 f32 -> 16B hi chunk + 16B lo chunk
__device__ __forceinline__ void cvt_split16(float4 a, float4 b, uint4& hi, uint4& lo) {
    __half2 h0 = __floats2half2_rn(a.x, a.y);
    __half2 h1 = __floats2half2_rn(a.z, a.w);
    __half2 h2 = __floats2half2_rn(b.x, b.y);
    __half2 h3 = __floats2half2_rn(b.z, b.w);
    float2 f0 = __half22float2(h0);
    float2 f1 = __half22float2(h1);
    float2 f2 = __half22float2(h2);
    float2 f3 = __half22float2(h3);
    __half2 l0 = __floats2half2_rn(a.x - f0.x, a.y - f0.y);
    __half2 l1 = __floats2half2_rn(a.z - f1.x, a.w - f1.y);
    __half2 l2 = __floats2half2_rn(b.x - f2.x, b.y - f2.y);
    __half2 l3 = __floats2half2_rn(b.z - f3.x, b.w - f3.y);
    hi.x = *(uint32_t*)&h0; hi.y = *(uint32_t*)&h1;
    hi.z = *(uint32_t*)&h2; hi.w = *(uint32_t*)&h3;
    lo.x = *(uint32_t*)&l0; lo.y = *(uint32_t*)&l1;
    lo.z = *(uint32_t*)&l2; lo.w = *(uint32_t*)&l3;
}
// round 8 f32 -> 16B fp16 chunk (hi only)
__device__ __forceinline__ void cvt_hi16(float4 a, float4 b, uint4& hi) {
    __half2 h0 = __floats2half2_rn(a.x, a.y);
    __half2 h1 = __floats2half2_rn(a.z, a.w);
    __half2 h2 = __floats2half2_rn(b.x, b.y);
    __half2 h3 = __floats2half2_rn(b.z, b.w);
    hi.x = *(uint32_t*)&h0; hi.y = *(uint32_t*)&h1;
    hi.z = *(uint32_t*)&h2; hi.w = *(uint32_t*)&h3;
}

// ============================================================
// BK=64 warp-specialized 2-MMA split GEMM (big GEMMs):
// C = Ah*Bh + Ah*Bl. CTA tile 128x128, BK=64, 2-stage ring.
// Planes: 128 rows x 128B, swizzle chunk c at (c ^ (r&7)).
// 384 threads: warps 0-7 consumers (64x32 warp tiles), 8-11 producers.
// ============================================================
#define T64B 16384                    // one plane: 128 rows x 128B
#define STG64B (3*T64B)               // A_hi, B_hi, B_lo = 49152
#define GEMM64_SMEM (2*STG64B)        // 98304

template<bool BIAS>
__global__ __launch_bounds__(384, 1)
void gemm_ws64(const float* __restrict__ A, long Ab, int lda,
               const float* __restrict__ B, long Bb, int ldb,
               float* __restrict__ C, long Cb, int ldc,
               const float* __restrict__ bias, int Kd)
{
    extern __shared__ __align__(16) char smc[];

    const int tid  = threadIdx.x;
    const int lane = tid & 31;
    const int wid  = tid >> 5;

    A += (size_t)blockIdx.z * Ab;
    B += (size_t)blockIdx.z * Bb;
    C += (size_t)blockIdx.z * Cb;
    const int m0 = blockIdx.y * 128;
    const int n0 = blockIdx.x * 128;
    const int iters = Kd / 64;

    if (wid >= 8) {
        // ================= producers (4 warps, 128 threads) =================
        const int ptid = tid - 256;
        const float* Aip = A + (size_t)m0 * lda;
        const float* Bip = B + (size_t)n0 * ldb;

        for (int it = 0; it < iters; it++) {
            const int s = it & 1;
            if (it >= 2) BAR_SYNC(4 + s);             // EMPTY(s)
            const int k0 = it * 64;
            char* stg = smc + s * STG64B;
            // A: 1024 positions (r 0..127, c 0..7), hi only; 8 per thread
            #pragma unroll
            for (int p = 0; p < 8; p++) {
                int idx = ptid + p * 128;             // 0..1023
                int r = idx >> 3, c = idx & 7;
                int sw = r * 128 + ((c ^ (r & 7)) << 4);
                const float* src = Aip + (size_t)r * lda + k0 + c * 8;
                float4 v0 = *(const float4*)src;
                float4 v1 = *(const float4*)(src + 4);
                uint4 hi;
                cvt_hi16(v0, v1, hi);
                *(uint4*)(stg + sw) = hi;
            }
            // B: 1024 positions, hi+lo; 8 per thread
            #pragma unroll
            for (int p = 0; p < 8; p++) {
                int idx = ptid + p * 128;
                int r = idx >> 3, c = idx & 7;
                int sw = r * 128 + ((c ^ (r & 7)) << 4);
                const float* src = Bip + (size_t)r * ldb + k0 + c * 8;
                float4 v0 = *(const float4*)src;
                float4 v1 = *(const float4*)(src + 4);
                uint4 hi, lo;
                cvt_split16(v0, v1, hi, lo);
                *(uint4*)(stg + T64B + sw) = hi;
                *(uint4*)(stg + 2*T64B + sw) = lo;
            }
            BAR_ARRIVE(1 + s);                        // FULL(s)
        }
    } else {
        // ================= consumers (8 warps, 64x32 warp tiles) ============
        const int wm = wid >> 2;
        const int wn = wid & 3;
        const int g  = lane >> 2;
        const int tig = lane & 3;
        const uint32_t sbase = smem_u32(smc);

        float acc[4][4][4];
        #pragma unroll
        for (int i = 0; i < 4; i++)
            #pragma unroll
            for (int j = 0; j < 4; j++)
                #pragma unroll
                for (int v = 0; v < 4; v++) acc[i][j][v] = 0.f;

        for (int it = 0; it < iters; it++) {
            const int s = it & 1;
            BAR_SYNC(1 + s);                          // FULL(s)
            const uint32_t stg = sbase + s * STG64B;

            #pragma unroll
            for (int kp = 0; kp < 2; kp++) {          // pairs of 16-k steps
                uint32_t ah[2][4][4], bh[2][4][2], bl[2][4][2];
                #pragma unroll
                for (int i = 0; i < 2; i++) {
                    const int kt = kp * 2 + i;
                    const int cA = kt * 2 + (lane >> 4);
                    #pragma unroll
                    for (int mi = 0; mi < 4; mi++) {
                        int r = wm * 64 + mi * 16 + (lane & 15);
                        uint32_t off = (uint32_t)(r * 128 + ((cA ^ (r & 7)) << 4));
                        ldsm4(ah[i][mi], stg + off);
                    }
                    const int cB = kt * 2 + ((lane >> 3) & 1);
                    #pragma unroll
                    for (int ni = 0; ni < 4; ni++) {
                        int r = wn * 32 + ni * 8 + (lane & 7);
                        uint32_t off = (uint32_t)(r * 128 + ((cB ^ (r & 7)) << 4));
                        ldsm2(bh[i][ni], stg + T64B + off);
                        ldsm2(bl[i][ni], stg + 2*T64B + off);
                    }
                }
                #pragma unroll
                for (int i = 0; i < 2; i++)
                    #pragma unroll
                    for (int mi = 0; mi < 4; mi++)
                        #pragma unroll
                        for (int ni = 0; ni < 4; ni++) {
                            mma16816(acc[mi][ni], ah[i][mi], bh[i][ni]);
                            mma16816(acc[mi][ni], ah[i][mi], bl[i][ni]);
                        }
            }
            BAR_ARRIVE(4 + s);                        // EMPTY(s)
        }

        // ---- epilogue ----
        #pragma unroll
        for (int mi = 0; mi < 4; mi++) {
            const int r0 = m0 + wm * 64 + mi * 16 + g;
            #pragma unroll
            for (int ni = 0; ni < 4; ni++) {
                const int col = n0 + wn * 32 + ni * 8 + tig * 2;
                float2 v0, v1;
                v0.x = acc[mi][ni][0]; v0.y = acc[mi][ni][1];
                v1.x = acc[mi][ni][2]; v1.y = acc[mi][ni][3];
                if (BIAS) {
                    float2 bv = *(const float2*)(bias + col);
                    v0.x += bv.x; v0.y += bv.y;
                    v1.x += bv.x; v1.y += bv.y;
                }
                *(float2*)(C + (size_t)r0 * ldc + col) = v0;
                *(float2*)(C + (size_t)(r0 + 8) * ldc + col) = v1;
            }
        }
    }
}

// ============================================================
// 128x128 BK=32 warp-specialized 2-MMA split GEMM (proj GEMMs, R9-proven)
// ============================================================
#define TILEB 8192
#define STGB  (3*TILEB)
#define NSTG  3
#define GEMM_SMEM (NSTG*STGB)        // 73728

__global__ __launch_bounds__(384, 1)
void gemm_ws(const float* __restrict__ A, long Ab, int lda,
             const float* __restrict__ B, long Bb, int ldb,
             float* __restrict__ C, long Cb, long Cs, int ldc,
             int Kd, int ksp)
{
    extern __shared__ __align__(16) char smc[];

    const int tid  = threadIdx.x;
    const int lane = tid & 31;
    const int wid  = tid >> 5;

    const int zb = blockIdx.z / ksp;
    const int zs = blockIdx.z % ksp;
    A += (size_t)zb * Ab + (size_t)zs * Kd;
    B += (size_t)zb * Bb + (size_t)zs * Kd;
    C += (size_t)zb * Cb + (size_t)zs * Cs;
    const int m0 = blockIdx.y * 128;
    const int n0 = blockIdx.x * 128;
    const int iters = Kd / 32;

    if (wid >= 8) {
        const int ptid = tid - 256;
        const float* Aip = A + (size_t)m0 * lda;
        const float* Bip = B + (size_t)n0 * ldb;

        for (int it = 0; it < iters; it++) {
            const int s = it % NSTG;
            if (it >= NSTG) BAR_SYNC(4 + s);
            const int k0 = it * 32;
            char* stg = smc + s * STGB;
            #pragma unroll
            for (int p = 0; p < 4; p++) {
                int idx = ptid + p * 128;
                int r = idx >> 2, c = idx & 3;
                int sw = (c ^ ((r >> 1) & 3)) * 16;
                {
                    const float* src = Aip + (size_t)r * lda + k0 + c * 8;
                    float4 v0 = *(const float4*)src;
                    float4 v1 = *(const float4*)(src + 4);
                    uint4 hi;
                    cvt_hi16(v0, v1, hi);
                    *(uint4*)(stg + r * 64 + sw) = hi;
                }
                {
                    const float* src = Bip + (size_t)r * ldb + k0 + c * 8;
                    float4 v0 = *(const float4*)src;
                    float4 v1 = *(const float4*)(src + 4);
                    uint4 hi, lo;
                    cvt_split16(v0, v1, hi, lo);
                    *(uint4*)(stg + TILEB + r * 64 + sw) = hi;
                    *(uint4*)(stg + 2*TILEB + r * 64 + sw) = lo;
                }
            }
            BAR_ARRIVE(1 + s);
        }
    } else {
        const int wm = wid >> 2;
        const int wn = wid & 3;
        const int g  = lane >> 2;
        const int tig = lane & 3;
        const uint32_t sbase = smem_u32(smc);

        float acc[4][4][4];
        #pragma unroll
        for (int i = 0; i < 4; i++)
            #pragma unroll
            for (int j = 0; j < 4; j++)
                #pragma unroll
                for (int v = 0; v < 4; v++) acc[i][j][v] = 0.f;

        for (int it = 0; it < iters; it++) {
            const int s = it % NSTG;
            BAR_SYNC(1 + s);
            const uint32_t stg = sbase + s * STGB;

            uint32_t ah[2][4][4], bh[2][4][2], bl[2][4][2];
            #pragma unroll
            for (int ks = 0; ks < 2; ks++) {
                const int cA = ks * 2 + (lane >> 4);
                #pragma unroll
                for (int mi = 0; mi < 4; mi++) {
                    int r = wm * 64 + mi * 16 + (lane & 15);
                    uint32_t off = (uint32_t)(r * 64 + ((cA ^ ((r >> 1) & 3)) << 4));
                    ldsm4(ah[ks][mi], stg + off);
                }
                const int cB = ks * 2 + ((lane >> 3) & 1);
                #pragma unroll
                for (int ni = 0; ni < 4; ni++) {
                    int r = wn * 32 + ni * 8 + (lane & 7);
                    uint32_t off = (uint32_t)(r * 64 + ((cB ^ ((r >> 1) & 3)) << 4));
                    ldsm2(bh[ks][ni], stg + TILEB + off);
                    ldsm2(bl[ks][ni], stg + 2*TILEB + off);
                }
            }
            #pragma unroll
            for (int ks = 0; ks < 2; ks++)
                #pragma unroll
                for (int mi = 0; mi < 4; mi++)
                    #pragma unroll
                    for (int ni = 0; ni < 4; ni++) {
                        mma16816(acc[mi][ni], ah[ks][mi], bh[ks][ni]);
                        mma16816(acc[mi][ni], ah[ks][mi], bl[ks][ni]);
                    }
            BAR_ARRIVE(4 + s);
        }

        #pragma unroll
        for (int mi = 0; mi < 4; mi++) {
            const int r0 = m0 + wm * 64 + mi * 16 + g;
            #pragma unroll
            for (int ni = 0; ni < 4; ni++) {
                const int col = n0 + wn * 32 + ni * 8 + tig * 2;
                float2 v0, v1;
                v0.x = acc[mi][ni][0]; v0.y = acc[mi][ni][1];
                v1.x = acc[mi][ni][2]; v1.y = acc[mi][ni][3];
                *(float2*)(C + (size_t)r0 * ldc + col) = v0;
                *(float2*)(C + (size_t)(r0 + 8) * ldc + col) = v1;
            }
        }
    }
}

// ============================================================
// proj transpose: [L,K] -> [K,L]
// ============================================================
__global__ __launch_bounds__(256)
void transpose_proj(const float* __restrict__ pk, const float* __restrict__ pv,
                    float* __restrict__ okt, float* __restrict__ ovt)
{
    __shared__ float t[32][33];
    const float* src = blockIdx.z ? pv : pk;
    float* dst       = blockIdx.z ? ovt : okt;
    int k0 = blockIdx.x * 32, l0 = blockIdx.y * 32;
    int tx = threadIdx.x, ty = threadIdx.y;
    #pragma unroll
    for (int i = 0; i < 32; i += 8)
        t[ty + i][tx] = src[(size_t)(l0 + ty + i) * KK + k0 + tx];
    __syncthreads();
    #pragma unroll
    for (int i = 0; i < 32; i += 8)
        dst[(size_t)(k0 + ty + i) * LL + l0 + tx] = t[tx][ty + i];
}

// ============================================================
// MMA attention (XOR-swizzled smem); split-K reduction FUSED into the
// K/V smem fill (reads both keys2/vals2 partials, adds, splits).
// ============================================================
#define AQH 0
#define AQL 16384
#define AKH 32768
#define AKL 65536
#define AVH 98304
#define AVL 131072
#define ATTN_SMEM 163840

__global__ __launch_bounds__(256, 1)
void attn_mma()
{
    extern __shared__ __align__(16) char smc[];
    const uint32_t base = smem_u32(smc);

    const int b  = blockIdx.z;
    const int h  = blockIdx.y;
    const int l0 = blockIdx.x * 128;
    const int tid  = threadIdx.x;
    const int lane = tid & 31;
    const int wy   = tid >> 5;
    const int g    = lane >> 2;
    const int tig  = lane & 3;

    #pragma unroll
    for (int it = 0; it < 4; it++) {
        int idx = tid + it * 256;
        int r = idx >> 3, c = idx & 7;
        int l = l0 + r;
        const float* src = g_q + ((size_t)(b * LL) + h * 128 + (l >> 4)) * DD
                               + (l & 15) * DH + c * 8;
        float4 v0 = *(const float4*)src;
        float4 v1 = *(const float4*)(src + 4);
        uint4 hi, lo;
        cvt_split16(v0, v1, hi, lo);
        int sw = r * 128 + ((c ^ (r & 7)) << 4);
        *(uint4*)(smc + AQH + sw) = hi;
        *(uint4*)(smc + AQL + sw) = lo;
    }
    const size_t PART = (size_t)BB * KK * DD;
    #pragma unroll
    for (int it = 0; it < 8; it++) {
        int idx = tid + it * 256;
        int r = idx >> 3, c = idx & 7;
        size_t o = ((size_t)b * KK + r) * DD + h * DH + c * 8;
        float4 a0 = *(const float4*)&g_keys2[o];
        float4 a1 = *(const float4*)&g_keys2[o + 4];
        float4 b0 = *(const float4*)&g_keys2[PART + o];
        float4 b1 = *(const float4*)&g_keys2[PART + o + 4];
        a0.x += b0.x; a0.y += b0.y; a0.z += b0.z; a0.w += b0.w;
        a1.x += b1.x; a1.y += b1.y; a1.z += b1.z; a1.w += b1.w;
        uint4 hi, lo;
        cvt_split16(a0, a1, hi, lo);
        int sw = r * 128 + ((c ^ (r & 7)) << 4);
        *(uint4*)(smc + AKH + sw) = hi;
        *(uint4*)(smc + AKL + sw) = lo;
    }
    #pragma unroll
    for (int it = 0; it < 8; it++) {
        int idx = tid + it * 256;
        int r = idx >> 3, c = idx & 7;
        size_t o = ((size_t)b * KK + r) * DD + h * DH + c * 8;
        float4 a0 = *(const float4*)&g_vals2[o];
        float4 a1 = *(const float4*)&g_vals2[o + 4];
        float4 b0 = *(const float4*)&g_vals2[PART + o];
        float4 b1 = *(const float4*)&g_vals2[PART + o + 4];
        a0.x += b0.x; a0.y += b0.y; a0.z += b0.z; a0.w += b0.w;
        a1.x += b1.x; a1.y += b1.y; a1.z += b1.z; a1.w += b1.w;
        uint4 hi, lo;
        cvt_split16(a0, a1, hi, lo);
        int sw = r * 128 + ((c ^ (r & 7)) << 4);
        *(uint4*)(smc + AVH + sw) = hi;
        *(uint4*)(smc + AVL + sw) = lo;
    }
    __syncthreads();

    const int m0w = wy * 16;

    uint32_t qa_h[4][4], qa_l[4][4];
    {
        int r = m0w + (lane & 15);
        #pragma unroll
        for (int kt = 0; kt < 4; kt++) {
            int c = kt * 2 + (lane >> 4);
            uint32_t off = (uint32_t)(r * 128 + ((c ^ (r & 7)) << 4));
            ldsm4(qa_h[kt], base + AQH + off);
            ldsm4(qa_l[kt], base + AQL + off);
        }
    }

    float acc[32][4];
    #pragma unroll
    for (int nt = 0; nt < 32; nt++)
        #pragma unroll
        for (int v = 0; v < 4; v++) acc[nt][v] = 0.f;

    #pragma unroll
    for (int nt = 0; nt < 32; nt++) {
        int r = nt * 8 + (lane & 7);
        int c0 = (lane >> 3);
        uint32_t off1 = (uint32_t)(r * 128 + ((c0 ^ (r & 7)) << 4));
        uint32_t off2 = (uint32_t)(r * 128 + (((c0 + 4) ^ (r & 7)) << 4));
        uint32_t kh[8], kl[8];
        ldsm4(kh,     base + AKH + off1);
        ldsm4(kh + 4, base + AKH + off2);
        ldsm4(kl,     base + AKL + off1);
        ldsm4(kl + 4, base + AKL + off2);
        #pragma unroll
        for (int kt = 0; kt < 4; kt++) {
            mma16816(acc[nt], qa_h[kt], kh + kt * 2);
            mma16816(acc[nt], qa_h[kt], kl + kt * 2);
            mma16816(acc[nt], qa_l[kt], kh + kt * 2);
        }
    }

    const float SC = 0.125f;
    float mx0 = -1e30f, mx1 = -1e30f;
    #pragma unroll
    for (int nt = 0; nt < 32; nt++) {
        mx0 = fmaxf(mx0, fmaxf(acc[nt][0], acc[nt][1]));
        mx1 = fmaxf(mx1, fmaxf(acc[nt][2], acc[nt][3]));
    }
    #pragma unroll
    for (int o = 1; o <= 2; o <<= 1) {
        mx0 = fmaxf(mx0, __shfl_xor_sync(0xffffffffu, mx0, o));
        mx1 = fmaxf(mx1, __shfl_xor_sync(0xffffffffu, mx1, o));
    }
    const float b0s = mx0 * SC, b1s = mx1 * SC;
    float s0 = 0.f, s1 = 0.f;
    #pragma unroll
    for (int nt = 0; nt < 32; nt++) {
        acc[nt][0] = __expf(acc[nt][0] * SC - b0s);
        acc[nt][1] = __expf(acc[nt][1] * SC - b0s);
        acc[nt][2] = __expf(acc[nt][2] * SC - b1s);
        acc[nt][3] = __expf(acc[nt][3] * SC - b1s);
        s0 += acc[nt][0] + acc[nt][1];
        s1 += acc[nt][2] + acc[nt][3];
    }
    #pragma unroll
    for (int o = 1; o <= 2; o <<= 1) {
        s0 += __shfl_xor_sync(0xffffffffu, s0, o);
        s1 += __shfl_xor_sync(0xffffffffu, s1, o);
    }
    const float inv0 = 1.f / s0, inv1 = 1.f / s1;

    float oac[8][4];
    #pragma unroll
    for (int nj = 0; nj < 8; nj++)
        #pragma unroll
        for (int v = 0; v < 4; v++) oac[nj][v] = 0.f;

    #pragma unroll
    for (int kt = 0; kt < 16; kt++) {
        uint32_t ph[4], pl[4];
        #pragma unroll
        for (int half_ = 0; half_ < 2; half_++) {
            const float* c = acc[2 * kt + half_];
            __half2 h0 = __floats2half2_rn(c[0], c[1]);
            __half2 h1 = __floats2half2_rn(c[2], c[3]);
            float2 f0 = __half22float2(h0);
            float2 f1 = __half22float2(h1);
            __half2 e0 = __floats2half2_rn(c[0] - f0.x, c[1] - f0.y);
            __half2 e1 = __floats2half2_rn(c[2] - f1.x, c[3] - f1.y);
            ph[half_ * 2 + 0] = *(uint32_t*)&h0;
            ph[half_ * 2 + 1] = *(uint32_t*)&h1;
            pl[half_ * 2 + 0] = *(uint32_t*)&e0;
            pl[half_ * 2 + 1] = *(uint32_t*)&e1;
        }
        int rv = kt * 16 + (lane & 15);
        #pragma unroll
        for (int nj = 0; nj < 8; nj++) {
            uint32_t off = (uint32_t)(rv * 128 + ((nj ^ (rv & 7)) << 4));
            uint32_t vh[2], vl[2];
            ldsm2t(vh, base + AVH + off);
            ldsm2t(vl, base + AVL + off);
            mma16816(oac[nj], ph, vh);
            mma16816(oac[nj], ph, vl);
            mma16816(oac[nj], pl, vh);
        }
    }

    {
        const int r0 = l0 + m0w + g;
        const size_t orow = ((size_t)(b * LL) + r0) * DD + h * DH;
        #pragma unroll
        for (int nj = 0; nj < 8; nj++) {
            float2 v0, v1;
            v0.x = oac[nj][0] * inv0; v0.y = oac[nj][1] * inv0;
            v1.x = oac[nj][2] * inv1; v1.y = oac[nj][3] * inv1;
            *(float2*)&g_ctx[orow + nj * 8 + tig * 2] = v0;
            *(float2*)&g_ctx[orow + (size_t)8 * DD + nj * 8 + tig * 2] = v1;
        }
    }
}

// ============================================================
extern "C" void kernel_launch(void* const* d_in, const int* in_sizes, int n_in,
                              void* d_out, int out_size)
{
    const float* x      = (const float*)d_in[0];
    const float* Wq     = (const float*)d_in[1];
    const float* Wk     = (const float*)d_in[2];
    const float* Wv     = (const float*)d_in[3];
    const float* proj_k = (const float*)d_in[4];
    const float* proj_v = (const float*)d_in[5];
    const float* Wo     = (const float*)d_in[6];
    const float* bo     = (const float*)d_in[7];
    float* out = (float*)d_out;

    float *q, *xkt, *xvt, *projkt, *projvt, *keys2, *vals2, *ctx;
    cudaGetSymbolAddress((void**)&q,      g_q);
    cudaGetSymbolAddress((void**)&xkt,    g_xkt);
    cudaGetSymbolAddress((void**)&xvt,    g_xvt);
    cudaGetSymbolAddress((void**)&projkt, g_projkt);
    cudaGetSymbolAddress((void**)&projvt, g_projvt);
    cudaGetSymbolAddress((void**)&keys2,  g_keys2);
    cudaGetSymbolAddress((void**)&vals2,  g_vals2);
    cudaGetSymbolAddress((void**)&ctx,    g_ctx);

    cudaFuncSetAttribute(gemm_ws64<false>, cudaFuncAttributeMaxDynamicSharedMemorySize, GEMM64_SMEM);
    cudaFuncSetAttribute(gemm_ws64<true>,  cudaFuncAttributeMaxDynamicSharedMemorySize, GEMM64_SMEM);
    cudaFuncSetAttribute(gemm_ws,  cudaFuncAttributeMaxDynamicSharedMemorySize, GEMM_SMEM);
    cudaFuncSetAttribute(attn_mma, cudaFuncAttributeMaxDynamicSharedMemorySize, ATTN_SMEM);

    // proj_k / proj_v -> transposed [K,L]
    transpose_proj<<<dim3(KK/32, LL/32, 2), dim3(32, 8)>>>(proj_k, proj_v, projkt, projvt);

    // q = x @ Wq^T
    gemm_ws64<false><<<dim3(DD/128, MROWS/128, 1), 384, GEMM64_SMEM>>>(
        x, 0, DD, Wq, 0, DD, q, 0, DD, nullptr, DD);

    // xkt[b] = Wk x_b^T : [D, L]
    gemm_ws64<false><<<dim3(LL/128, DD/128, BB), 384, GEMM64_SMEM>>>(
        Wk, 0, DD, x, (long)LL*DD, DD, xkt, (long)DD*LL, LL, nullptr, DD);

    // xvt[b]
    gemm_ws64<false><<<dim3(LL/128, DD/128, BB), 384, GEMM64_SMEM>>>(
        Wv, 0, DD, x, (long)LL*DD, DD, xvt, (long)DD*LL, LL, nullptr, DD);

    // keys partials [zs][b][K,D] = projkt x xkt^T  (split-K over L)
    gemm_ws<<<dim3(DD/128, KK/128, BB*2), 384, GEMM_SMEM>>>(
        projkt, 0, LL, xkt, (long)DD*LL, LL,
        keys2, (long)KK*DD, (long)BB*KK*DD, DD, LL/2, 2);

    // vals partials [zs][b][K,D]
    gemm_ws<<<dim3(DD/128, KK/128, BB*2), 384, GEMM_SMEM>>>(
        projvt, 0, LL, xvt, (long)DD*LL, LL,
        vals2, (long)KK*DD, (long)BB*KK*DD, DD, LL/2, 2);

    // MMA attention (fuses the split-K adds)
    attn_mma<<<dim3(LL/128, HH, BB), 256, ATTN_SMEM>>>();

    // out = ctx @ Wo^T + bo
    gemm_ws64<true><<<dim3(DD/128, MROWS/128, 1), 384, GEMM64_SMEM>>>(
        ctx, 0, DD, Wo, 0, DD, out, 0, DD, bo, DD);
}